// round 1
// baseline (speedup 1.0000x reference)
#include <cuda_runtime.h>

#define SQ    8192      // sequence length
#define DH    64        // head dim
#define NHB   16        // B * H = 2 * 8
#define M_TOT 16384     // B * S
#define DM    512       // model dim

// Scratch (allocation-free rule: __device__ globals). 4 x 33.5 MB = 134 MB.
__device__ float g_q[(size_t)NHB * SQ * DH];
__device__ float g_k[(size_t)NHB * SQ * DH];
__device__ float g_v[(size_t)NHB * SQ * DH];
__device__ float g_o[(size_t)NHB * SQ * DH];

// ---------------------------------------------------------------------------
// QKV projection: C = hs @ W  for W in {wq, wk, wv}; q scaled by 1/sqrt(64).
// Output written head-major: g_x[((b*8+h)*SQ + s)*DH + d].
// 128x128 tile, K-step 8, 256 threads, 8x8 per thread.
// ---------------------------------------------------------------------------
__global__ __launch_bounds__(256) void qkv_gemm(
    const float* __restrict__ hs,
    const float* __restrict__ wq,
    const float* __restrict__ wk,
    const float* __restrict__ wv)
{
    const int which = blockIdx.z;
    const float* __restrict__ w = (which == 0) ? wq : (which == 1) ? wk : wv;
    float* __restrict__ outb = (which == 0) ? g_q : (which == 1) ? g_k : g_v;
    const float scale = (which == 0) ? 0.125f : 1.0f;

    __shared__ float As[8][128];
    __shared__ float Bs[8][128];

    const int tid  = threadIdx.x;
    const int row0 = blockIdx.y * 128;
    const int col0 = blockIdx.x * 128;
    const int tx = tid & 15, ty = tid >> 4;

    float acc[8][8];
#pragma unroll
    for (int i = 0; i < 8; i++)
#pragma unroll
        for (int j = 0; j < 8; j++) acc[i][j] = 0.f;

    const int ar = tid >> 1, ak = (tid & 1) * 4;
    const int bk = tid >> 5, bc = (tid & 31) * 4;

    for (int kt = 0; kt < DM; kt += 8) {
        float4 av = *(const float4*)&hs[(size_t)(row0 + ar) * DM + kt + ak];
        As[ak + 0][ar] = av.x; As[ak + 1][ar] = av.y;
        As[ak + 2][ar] = av.z; As[ak + 3][ar] = av.w;
        float4 bv = *(const float4*)&w[(size_t)(kt + bk) * DM + col0 + bc];
        *(float4*)&Bs[bk][bc] = bv;
        __syncthreads();
#pragma unroll
        for (int k = 0; k < 8; k++) {
            float a[8], b[8];
            *(float4*)&a[0] = *(const float4*)&As[k][ty * 8];
            *(float4*)&a[4] = *(const float4*)&As[k][ty * 8 + 4];
            *(float4*)&b[0] = *(const float4*)&Bs[k][tx * 8];
            *(float4*)&b[4] = *(const float4*)&Bs[k][tx * 8 + 4];
#pragma unroll
            for (int i = 0; i < 8; i++)
#pragma unroll
                for (int j = 0; j < 8; j++) acc[i][j] += a[i] * b[j];
        }
        __syncthreads();
    }

#pragma unroll
    for (int i = 0; i < 8; i++) {
        const int m = row0 + ty * 8 + i;
        const int b = m >> 13, s = m & (SQ - 1);
#pragma unroll
        for (int j4 = 0; j4 < 8; j4 += 4) {
            const int n = col0 + tx * 8 + j4;
            const int h = n >> 6, d = n & 63;
            float4 o4 = make_float4(acc[i][j4 + 0] * scale, acc[i][j4 + 1] * scale,
                                    acc[i][j4 + 2] * scale, acc[i][j4 + 3] * scale);
            *(float4*)&outb[(((size_t)(b * 8 + h)) * SQ + s) * DH + d] = o4;
        }
    }
}

// ---------------------------------------------------------------------------
// Flash attention (fp32, online softmax). grid (S/64, NHB), 128 threads.
// Per block: 64 q-rows x full dh=64. K/V tiles of 64 keys staged in smem.
// Thread (ty in 0..7, tx in 0..15) owns 8 rows x 4 cols of S and of O.
// ---------------------------------------------------------------------------
#define ATTN_SMEM ((3 * 64 * 68 + 64 * 64) * 4)

__global__ __launch_bounds__(128) void attn_kernel()
{
    extern __shared__ __align__(16) float sm[];
    float (*qs)[68] = (float(*)[68])sm;                    // [d][r], padded
    float (*ks)[68] = (float(*)[68])(sm + 64 * 68);        // [d][c], padded
    float (*ps)[68] = (float(*)[68])(sm + 2 * 64 * 68);    // [c][r], padded
    float (*vs)[64] = (float(*)[64])(sm + 3 * 64 * 68);    // [c][d], unpadded (float4 rows)

    const int head = blockIdx.y;
    const size_t hbase = (size_t)head * SQ * DH;
    const float* __restrict__ Q = g_q + hbase;
    const float* __restrict__ K = g_k + hbase;
    const float* __restrict__ V = g_v + hbase;

    const int q0  = blockIdx.x * 64;
    const int tid = threadIdx.x;
    const int tx = tid & 15, ty = tid >> 4;   // ty: 0..7 row groups, tx: 0..15 col groups

    // Load Q tile transposed into smem: qs[d][r]
    for (int i = tid; i < 64 * 16; i += 128) {
        const int r = i >> 4, d4 = (i & 15) * 4;
        float4 v4 = *(const float4*)&Q[(size_t)(q0 + r) * DH + d4];
        qs[d4 + 0][r] = v4.x; qs[d4 + 1][r] = v4.y;
        qs[d4 + 2][r] = v4.z; qs[d4 + 3][r] = v4.w;
    }

    float m_r[8], l_r[8], o_acc[8][4];
#pragma unroll
    for (int i = 0; i < 8; i++) {
        m_r[i] = -1e30f; l_r[i] = 0.f;
#pragma unroll
        for (int j = 0; j < 4; j++) o_acc[i][j] = 0.f;
    }

    for (int kt = 0; kt < SQ; kt += 64) {
        __syncthreads();   // previous iteration's ks/vs/ps readers done (covers qs on iter 0 too)
        for (int i = tid; i < 64 * 16; i += 128) {
            const int c = i >> 4, d4 = (i & 15) * 4;
            float4 kv = *(const float4*)&K[(size_t)(kt + c) * DH + d4];
            ks[d4 + 0][c] = kv.x; ks[d4 + 1][c] = kv.y;
            ks[d4 + 2][c] = kv.z; ks[d4 + 3][c] = kv.w;
            float4 vv = *(const float4*)&V[(size_t)(kt + c) * DH + d4];
            *(float4*)&vs[c][d4] = vv;
        }
        __syncthreads();

        // S = Q K^T (64x64), 8x4 fragment per thread
        float s_f[8][4];
#pragma unroll
        for (int i = 0; i < 8; i++)
#pragma unroll
            for (int j = 0; j < 4; j++) s_f[i][j] = 0.f;

#pragma unroll 8
        for (int d = 0; d < 64; d++) {
            float a[8], bb[4];
            *(float4*)&a[0] = *(const float4*)&qs[d][ty * 8];
            *(float4*)&a[4] = *(const float4*)&qs[d][ty * 8 + 4];
            *(float4*)&bb[0] = *(const float4*)&ks[d][tx * 4];
#pragma unroll
            for (int i = 0; i < 8; i++)
#pragma unroll
                for (int j = 0; j < 4; j++) s_f[i][j] += a[i] * bb[j];
        }

        // Online softmax (row reductions across the 16 tx lanes; lane = (ty&1)*16 + tx,
        // so xor offsets 1,2,4,8 stay inside the row group)
#pragma unroll
        for (int i = 0; i < 8; i++) {
            float tm = fmaxf(fmaxf(s_f[i][0], s_f[i][1]), fmaxf(s_f[i][2], s_f[i][3]));
#pragma unroll
            for (int off = 8; off >= 1; off >>= 1)
                tm = fmaxf(tm, __shfl_xor_sync(0xffffffffu, tm, off));
            const float mn   = fmaxf(m_r[i], tm);
            const float corr = __expf(m_r[i] - mn);
            m_r[i] = mn;
            float rs = 0.f;
#pragma unroll
            for (int j = 0; j < 4; j++) {
                const float p = __expf(s_f[i][j] - mn);
                s_f[i][j] = p; rs += p;
            }
#pragma unroll
            for (int off = 8; off >= 1; off >>= 1)
                rs += __shfl_xor_sync(0xffffffffu, rs, off);
            l_r[i] = l_r[i] * corr + rs;
#pragma unroll
            for (int j = 0; j < 4; j++) o_acc[i][j] *= corr;
        }

        // P to smem as [c][r] for the O-gemm
#pragma unroll
        for (int i = 0; i < 8; i++)
#pragma unroll
            for (int j = 0; j < 4; j++)
                ps[tx * 4 + j][ty * 8 + i] = s_f[i][j];
        __syncthreads();

        // O += P V (64 keys x dh=64)
#pragma unroll 8
        for (int c = 0; c < 64; c++) {
            float pr[8], vv[4];
            *(float4*)&pr[0] = *(const float4*)&ps[c][ty * 8];
            *(float4*)&pr[4] = *(const float4*)&ps[c][ty * 8 + 4];
            *(float4*)&vv[0] = *(const float4*)&vs[c][tx * 4];
#pragma unroll
            for (int i = 0; i < 8; i++)
#pragma unroll
                for (int j = 0; j < 4; j++) o_acc[i][j] += pr[i] * vv[j];
        }
    }

    float* __restrict__ O = g_o + hbase;
#pragma unroll
    for (int i = 0; i < 8; i++) {
        const float inv = 1.f / l_r[i];
        float4 o4 = make_float4(o_acc[i][0] * inv, o_acc[i][1] * inv,
                                o_acc[i][2] * inv, o_acc[i][3] * inv);
        *(float4*)&O[(size_t)(q0 + ty * 8 + i) * DH + tx * 4] = o4;
    }
}

// ---------------------------------------------------------------------------
// Output projection: out = attn @ w_out + b_out.
// A(m, k) gathered from head-major g_o: k = h*64 + d.
// ---------------------------------------------------------------------------
__global__ __launch_bounds__(256) void out_gemm(
    const float* __restrict__ w,
    const float* __restrict__ bias,
    float* __restrict__ out)
{
    __shared__ float As[8][128];
    __shared__ float Bs[8][128];

    const int tid  = threadIdx.x;
    const int row0 = blockIdx.y * 128;
    const int col0 = blockIdx.x * 128;
    const int tx = tid & 15, ty = tid >> 4;

    float acc[8][8];
#pragma unroll
    for (int i = 0; i < 8; i++)
#pragma unroll
        for (int j = 0; j < 8; j++) acc[i][j] = 0.f;

    const int ar = tid >> 1, ak = (tid & 1) * 4;
    const int bk = tid >> 5, bc = (tid & 31) * 4;

    const int m = row0 + ar;
    const int b = m >> 13, s = m & (SQ - 1);
    const float* __restrict__ abase = g_o + ((size_t)(b * 8)) * SQ * DH + (size_t)s * DH;

    for (int kt = 0; kt < DM; kt += 8) {
        const int k = kt + ak;
        const int h = k >> 6, d = k & 63;   // the 4 loaded k's stay inside one head
        float4 av = *(const float4*)&abase[(size_t)h * SQ * DH + d];
        As[ak + 0][ar] = av.x; As[ak + 1][ar] = av.y;
        As[ak + 2][ar] = av.z; As[ak + 3][ar] = av.w;
        float4 bv = *(const float4*)&w[(size_t)(kt + bk) * DM + col0 + bc];
        *(float4*)&Bs[bk][bc] = bv;
        __syncthreads();
#pragma unroll
        for (int kk = 0; kk < 8; kk++) {
            float a[8], bb[8];
            *(float4*)&a[0] = *(const float4*)&As[kk][ty * 8];
            *(float4*)&a[4] = *(const float4*)&As[kk][ty * 8 + 4];
            *(float4*)&bb[0] = *(const float4*)&Bs[kk][tx * 8];
            *(float4*)&bb[4] = *(const float4*)&Bs[kk][tx * 8 + 4];
#pragma unroll
            for (int i = 0; i < 8; i++)
#pragma unroll
                for (int j = 0; j < 8; j++) acc[i][j] += a[i] * bb[j];
        }
        __syncthreads();
    }

#pragma unroll
    for (int i = 0; i < 8; i++) {
        const int mm = row0 + ty * 8 + i;
#pragma unroll
        for (int j4 = 0; j4 < 8; j4 += 4) {
            const int n = col0 + tx * 8 + j4;
            float4 o4 = make_float4(acc[i][j4 + 0] + bias[n + 0],
                                    acc[i][j4 + 1] + bias[n + 1],
                                    acc[i][j4 + 2] + bias[n + 2],
                                    acc[i][j4 + 3] + bias[n + 3]);
            *(float4*)&out[(size_t)mm * DM + n] = o4;
        }
    }
}

// ---------------------------------------------------------------------------
extern "C" void kernel_launch(void* const* d_in, const int* in_sizes, int n_in,
                              void* d_out, int out_size)
{
    const float* hs = (const float*)d_in[0];
    const float* wq = (const float*)d_in[1];
    const float* wk = (const float*)d_in[2];
    const float* wv = (const float*)d_in[3];
    const float* wo = (const float*)d_in[4];
    const float* bo = (const float*)d_in[5];
    float* out = (float*)d_out;

    cudaFuncSetAttribute(attn_kernel,
                         cudaFuncAttributeMaxDynamicSharedMemorySize, ATTN_SMEM);

    qkv_gemm<<<dim3(4, 128, 3), 256>>>(hs, wq, wk, wv);
    attn_kernel<<<dim3(SQ / 64, NHB), 128, ATTN_SMEM>>>();
    out_gemm<<<dim3(4, 128), 256>>>(wo, bo, out);
}

// round 2
// speedup vs baseline: 3.1152x; 3.1152x over previous
#include <cuda_runtime.h>

#define SQ    8192
#define DH    64
#define NHB   16
#define M_TOT 16384
#define DM    512

__device__ float g_q[(size_t)NHB * SQ * DH];
__device__ float g_k[(size_t)NHB * SQ * DH];
__device__ float g_v[(size_t)NHB * SQ * DH];
__device__ float g_o[(size_t)NHB * SQ * DH];

__device__ __forceinline__ unsigned f2tf(float x) {
    unsigned r; asm("cvt.rna.tf32.f32 %0, %1;" : "=r"(r) : "f"(x)); return r;
}

__device__ __forceinline__ void mma_tf32(float c[4], const unsigned a[4], const unsigned b[2]) {
    asm volatile("mma.sync.aligned.m16n8k8.row.col.f32.tf32.tf32.f32 "
                 "{%0,%1,%2,%3}, {%4,%5,%6,%7}, {%8,%9}, {%0,%1,%2,%3};\n"
                 : "+f"(c[0]), "+f"(c[1]), "+f"(c[2]), "+f"(c[3])
                 : "r"(a[0]), "r"(a[1]), "r"(a[2]), "r"(a[3]),
                   "r"(b[0]), "r"(b[1]));
}

// ---------------------------------------------------------------------------
// QKV projection with tf32 mma. C = hs @ W, q scaled by 1/8, head-major out.
// Block tile 128x128, BK=16, 256 threads (8 warps: 2 m x 4 n), warp 64x32.
// ---------------------------------------------------------------------------
__global__ __launch_bounds__(256) void qkv_gemm_tc(
    const float* __restrict__ hs,
    const float* __restrict__ wq,
    const float* __restrict__ wk,
    const float* __restrict__ wv)
{
    const int which = blockIdx.z;
    const float* __restrict__ w = (which == 0) ? wq : (which == 1) ? wk : wv;
    float* __restrict__ outb = (which == 0) ? g_q : (which == 1) ? g_k : g_v;
    const float scale = (which == 0) ? 0.125f : 1.0f;

    __shared__ unsigned As[16][136];   // [k][m], conflict-free frag loads
    __shared__ unsigned Bs[16][136];   // [k][n]

    const int tid  = threadIdx.x;
    const int wid  = tid >> 5;
    const int lane = tid & 31;
    const int gid  = lane >> 2;    // groupID 0..7
    const int tig  = lane & 3;     // thread-in-group 0..3
    const int wm = wid & 1, wn = wid >> 1;
    const int row0 = blockIdx.y * 128;
    const int col0 = blockIdx.x * 128;

    float acc[4][4][4];
#pragma unroll
    for (int i = 0; i < 4; i++)
#pragma unroll
        for (int j = 0; j < 4; j++)
#pragma unroll
            for (int p = 0; p < 4; p++) acc[i][j][p] = 0.f;

    const int am0 = wm * 64 + gid;
    const int bn0 = wn * 32 + gid;

    for (int kt = 0; kt < DM; kt += 16) {
        __syncthreads();
#pragma unroll
        for (int r = 0; r < 2; r++) {
            int idx = tid + r * 256;               // 0..511
            int m = idx >> 2, kq = idx & 3;
            float4 v = *(const float4*)&hs[(size_t)(row0 + m) * DM + kt + kq * 4];
            As[kq * 4 + 0][m] = f2tf(v.x);
            As[kq * 4 + 1][m] = f2tf(v.y);
            As[kq * 4 + 2][m] = f2tf(v.z);
            As[kq * 4 + 3][m] = f2tf(v.w);
            int kr = idx >> 5, c4 = idx & 31;
            float4 bv = *(const float4*)&w[(size_t)(kt + kr) * DM + col0 + c4 * 4];
            Bs[kr][c4 * 4 + 0] = f2tf(bv.x);
            Bs[kr][c4 * 4 + 1] = f2tf(bv.y);
            Bs[kr][c4 * 4 + 2] = f2tf(bv.z);
            Bs[kr][c4 * 4 + 3] = f2tf(bv.w);
        }
        __syncthreads();

#pragma unroll
        for (int kk = 0; kk < 16; kk += 8) {
            unsigned a[4][4], b[4][2];
#pragma unroll
            for (int mf = 0; mf < 4; mf++) {
                a[mf][0] = As[kk + tig][am0 + mf * 16];
                a[mf][1] = As[kk + tig][am0 + mf * 16 + 8];
                a[mf][2] = As[kk + tig + 4][am0 + mf * 16];
                a[mf][3] = As[kk + tig + 4][am0 + mf * 16 + 8];
            }
#pragma unroll
            for (int nf = 0; nf < 4; nf++) {
                b[nf][0] = Bs[kk + tig][bn0 + nf * 8];
                b[nf][1] = Bs[kk + tig + 4][bn0 + nf * 8];
            }
#pragma unroll
            for (int mf = 0; mf < 4; mf++)
#pragma unroll
                for (int nf = 0; nf < 4; nf++)
                    mma_tf32(acc[mf][nf], a[mf], b[nf]);
        }
    }

    // epilogue: head-major store
#pragma unroll
    for (int mf = 0; mf < 4; mf++) {
#pragma unroll
        for (int half = 0; half < 2; half++) {
            const int m = row0 + wm * 64 + mf * 16 + gid + half * 8;
            const int b = m >> 13, s = m & (SQ - 1);
            float* obase = outb + (((size_t)(b * 8)) * SQ) * DH + (size_t)s * DH;
#pragma unroll
            for (int nf = 0; nf < 4; nf++) {
                const int n = col0 + wn * 32 + nf * 8 + 2 * tig;
                const int h = n >> 6, d = n & 63;
                float2 o2 = make_float2(acc[mf][nf][half * 2] * scale,
                                        acc[mf][nf][half * 2 + 1] * scale);
                *(float2*)&obase[(size_t)h * SQ * DH + d] = o2;
            }
        }
    }
}

// ---------------------------------------------------------------------------
// Flash attention, tf32 mma. grid (SQ/64, NHB), 128 threads (4 warps).
// Warp w owns q rows [w*16, w*16+16). Q resident in registers as A-frags.
// ---------------------------------------------------------------------------
#define ATTN_SMEM ((64 * 68 + 64 * 72 + 64 * 68) * 4)

__global__ __launch_bounds__(128) void attn_tc()
{
    extern __shared__ __align__(16) unsigned smu[];
    unsigned (*Ks)[68] = (unsigned(*)[68])smu;                       // [key][d]
    unsigned (*Vs)[72] = (unsigned(*)[72])(smu + 64 * 68);           // [key][d]
    unsigned (*Ps)[68] = (unsigned(*)[68])(smu + 64 * 68 + 64 * 72); // [q][key]

    const int head = blockIdx.y;
    const size_t hbase = (size_t)head * SQ * DH;
    const float* __restrict__ Q = g_q + hbase;
    const float* __restrict__ K = g_k + hbase;
    const float* __restrict__ V = g_v + hbase;

    const int q0   = blockIdx.x * 64;
    const int tid  = threadIdx.x;
    const int wid  = tid >> 5;
    const int lane = tid & 31;
    const int gid  = lane >> 2;
    const int tig  = lane & 3;

    // Q fragments (resident): rows w*16+gid, w*16+gid+8
    unsigned qa[8][4];
    {
        const int r0 = q0 + wid * 16 + gid;
#pragma unroll
        for (int kk = 0; kk < 8; kk++) {
            qa[kk][0] = f2tf(__ldg(&Q[(size_t)r0 * DH + kk * 8 + tig]));
            qa[kk][1] = f2tf(__ldg(&Q[(size_t)(r0 + 8) * DH + kk * 8 + tig]));
            qa[kk][2] = f2tf(__ldg(&Q[(size_t)r0 * DH + kk * 8 + tig + 4]));
            qa[kk][3] = f2tf(__ldg(&Q[(size_t)(r0 + 8) * DH + kk * 8 + tig + 4]));
        }
    }

    float oa[8][4];
    float m0 = -1e30f, m1 = -1e30f, l0 = 0.f, l1 = 0.f;
#pragma unroll
    for (int n = 0; n < 8; n++)
#pragma unroll
        for (int p = 0; p < 4; p++) oa[n][p] = 0.f;

    for (int kt = 0; kt < SQ; kt += 64) {
        __syncthreads();
        // stage K, V (cvt to tf32)
        for (int i = tid; i < 64 * 16; i += 128) {
            const int c = i >> 4, d4 = (i & 15) * 4;
            float4 kv = *(const float4*)&K[(size_t)(kt + c) * DH + d4];
            uint4 ku = make_uint4(f2tf(kv.x), f2tf(kv.y), f2tf(kv.z), f2tf(kv.w));
            *(uint4*)&Ks[c][d4] = ku;
            float4 vv = *(const float4*)&V[(size_t)(kt + c) * DH + d4];
            uint4 vu = make_uint4(f2tf(vv.x), f2tf(vv.y), f2tf(vv.z), f2tf(vv.w));
            *(uint4*)&Vs[c][d4] = vu;
        }
        __syncthreads();

        // S = Q K^T : warp computes rows w*16..+16 x 64 keys
        float sa[8][4];
#pragma unroll
        for (int n = 0; n < 8; n++)
#pragma unroll
            for (int p = 0; p < 4; p++) sa[n][p] = 0.f;

#pragma unroll
        for (int n = 0; n < 8; n++) {
#pragma unroll
            for (int kk = 0; kk < 8; kk++) {
                unsigned b[2];
                b[0] = Ks[n * 8 + gid][kk * 8 + tig];
                b[1] = Ks[n * 8 + gid][kk * 8 + tig + 4];
                mma_tf32(sa[n], qa[kk], b);
            }
        }

        // online softmax (rows live in quads; reduce over xor 1,2)
        float tm0 = -1e30f, tm1 = -1e30f;
#pragma unroll
        for (int n = 0; n < 8; n++) {
            tm0 = fmaxf(tm0, fmaxf(sa[n][0], sa[n][1]));
            tm1 = fmaxf(tm1, fmaxf(sa[n][2], sa[n][3]));
        }
        tm0 = fmaxf(tm0, __shfl_xor_sync(0xffffffffu, tm0, 1));
        tm0 = fmaxf(tm0, __shfl_xor_sync(0xffffffffu, tm0, 2));
        tm1 = fmaxf(tm1, __shfl_xor_sync(0xffffffffu, tm1, 1));
        tm1 = fmaxf(tm1, __shfl_xor_sync(0xffffffffu, tm1, 2));

        const float mn0 = fmaxf(m0, tm0), mn1 = fmaxf(m1, tm1);
        const float corr0 = __expf(m0 - mn0), corr1 = __expf(m1 - mn1);
        m0 = mn0; m1 = mn1;

        float rs0 = 0.f, rs1 = 0.f;
#pragma unroll
        for (int n = 0; n < 8; n++) {
            sa[n][0] = __expf(sa[n][0] - mn0);
            sa[n][1] = __expf(sa[n][1] - mn0);
            sa[n][2] = __expf(sa[n][2] - mn1);
            sa[n][3] = __expf(sa[n][3] - mn1);
            rs0 += sa[n][0] + sa[n][1];
            rs1 += sa[n][2] + sa[n][3];
        }
        rs0 += __shfl_xor_sync(0xffffffffu, rs0, 1);
        rs0 += __shfl_xor_sync(0xffffffffu, rs0, 2);
        rs1 += __shfl_xor_sync(0xffffffffu, rs1, 1);
        rs1 += __shfl_xor_sync(0xffffffffu, rs1, 2);
        l0 = l0 * corr0 + rs0;
        l1 = l1 * corr1 + rs1;

#pragma unroll
        for (int n = 0; n < 8; n++) {
            oa[n][0] *= corr0; oa[n][1] *= corr0;
            oa[n][2] *= corr1; oa[n][3] *= corr1;
        }

        // P to smem (tf32); only this warp reads its own rows back
        const int pr = wid * 16 + gid;
#pragma unroll
        for (int n = 0; n < 8; n++) {
            Ps[pr][n * 8 + 2 * tig]         = f2tf(sa[n][0]);
            Ps[pr][n * 8 + 2 * tig + 1]     = f2tf(sa[n][1]);
            Ps[pr + 8][n * 8 + 2 * tig]     = f2tf(sa[n][2]);
            Ps[pr + 8][n * 8 + 2 * tig + 1] = f2tf(sa[n][3]);
        }
        __syncwarp();

        // O += P V
#pragma unroll
        for (int kk2 = 0; kk2 < 8; kk2++) {
            unsigned pa[4];
            pa[0] = Ps[wid * 16 + gid][kk2 * 8 + tig];
            pa[1] = Ps[wid * 16 + gid + 8][kk2 * 8 + tig];
            pa[2] = Ps[wid * 16 + gid][kk2 * 8 + tig + 4];
            pa[3] = Ps[wid * 16 + gid + 8][kk2 * 8 + tig + 4];
#pragma unroll
            for (int n = 0; n < 8; n++) {
                unsigned vb[2];
                vb[0] = Vs[kk2 * 8 + tig][n * 8 + gid];
                vb[1] = Vs[kk2 * 8 + tig + 4][n * 8 + gid];
                mma_tf32(oa[n], pa, vb);
            }
        }
    }

    // epilogue
    float* __restrict__ O = g_o + hbase;
    const float inv0 = 1.f / l0, inv1 = 1.f / l1;
    const int r0 = q0 + wid * 16 + gid;
#pragma unroll
    for (int n = 0; n < 8; n++) {
        const int col = n * 8 + 2 * tig;
        *(float2*)&O[(size_t)r0 * DH + col] =
            make_float2(oa[n][0] * inv0, oa[n][1] * inv0);
        *(float2*)&O[(size_t)(r0 + 8) * DH + col] =
            make_float2(oa[n][2] * inv1, oa[n][3] * inv1);
    }
}

// ---------------------------------------------------------------------------
// Output projection with tf32 mma: out = attn @ w_out + b_out.
// A gathered from head-major g_o.
// ---------------------------------------------------------------------------
__global__ __launch_bounds__(256) void out_gemm_tc(
    const float* __restrict__ w,
    const float* __restrict__ bias,
    float* __restrict__ out)
{
    __shared__ unsigned As[16][136];
    __shared__ unsigned Bs[16][136];

    const int tid  = threadIdx.x;
    const int wid  = tid >> 5;
    const int lane = tid & 31;
    const int gid  = lane >> 2;
    const int tig  = lane & 3;
    const int wm = wid & 1, wn = wid >> 1;
    const int row0 = blockIdx.y * 128;
    const int col0 = blockIdx.x * 128;

    float acc[4][4][4];
#pragma unroll
    for (int i = 0; i < 4; i++)
#pragma unroll
        for (int j = 0; j < 4; j++)
#pragma unroll
            for (int p = 0; p < 4; p++) acc[i][j][p] = 0.f;

    const int am0 = wm * 64 + gid;
    const int bn0 = wn * 32 + gid;

    for (int kt = 0; kt < DM; kt += 16) {
        __syncthreads();
#pragma unroll
        for (int r = 0; r < 2; r++) {
            int idx = tid + r * 256;
            int m = row0 + (idx >> 2), kq = idx & 3;
            int k = kt + kq * 4;
            int h = k >> 6, d = k & 63;
            int b = m >> 13, s = m & (SQ - 1);
            float4 v = *(const float4*)&g_o[(((size_t)(b * 8 + h)) * SQ + s) * DH + d];
            As[kq * 4 + 0][idx >> 2] = f2tf(v.x);
            As[kq * 4 + 1][idx >> 2] = f2tf(v.y);
            As[kq * 4 + 2][idx >> 2] = f2tf(v.z);
            As[kq * 4 + 3][idx >> 2] = f2tf(v.w);
            int kr = idx >> 5, c4 = idx & 31;
            float4 bv = *(const float4*)&w[(size_t)(kt + kr) * DM + col0 + c4 * 4];
            Bs[kr][c4 * 4 + 0] = f2tf(bv.x);
            Bs[kr][c4 * 4 + 1] = f2tf(bv.y);
            Bs[kr][c4 * 4 + 2] = f2tf(bv.z);
            Bs[kr][c4 * 4 + 3] = f2tf(bv.w);
        }
        __syncthreads();

#pragma unroll
        for (int kk = 0; kk < 16; kk += 8) {
            unsigned a[4][4], b[4][2];
#pragma unroll
            for (int mf = 0; mf < 4; mf++) {
                a[mf][0] = As[kk + tig][am0 + mf * 16];
                a[mf][1] = As[kk + tig][am0 + mf * 16 + 8];
                a[mf][2] = As[kk + tig + 4][am0 + mf * 16];
                a[mf][3] = As[kk + tig + 4][am0 + mf * 16 + 8];
            }
#pragma unroll
            for (int nf = 0; nf < 4; nf++) {
                b[nf][0] = Bs[kk + tig][bn0 + nf * 8];
                b[nf][1] = Bs[kk + tig + 4][bn0 + nf * 8];
            }
#pragma unroll
            for (int mf = 0; mf < 4; mf++)
#pragma unroll
                for (int nf = 0; nf < 4; nf++)
                    mma_tf32(acc[mf][nf], a[mf], b[nf]);
        }
    }

#pragma unroll
    for (int mf = 0; mf < 4; mf++) {
#pragma unroll
        for (int half = 0; half < 2; half++) {
            const int m = row0 + wm * 64 + mf * 16 + gid + half * 8;
#pragma unroll
            for (int nf = 0; nf < 4; nf++) {
                const int n = col0 + wn * 32 + nf * 8 + 2 * tig;
                float2 o2 = make_float2(acc[mf][nf][half * 2] + bias[n],
                                        acc[mf][nf][half * 2 + 1] + bias[n + 1]);
                *(float2*)&out[(size_t)m * DM + n] = o2;
            }
        }
    }
}

// ---------------------------------------------------------------------------
extern "C" void kernel_launch(void* const* d_in, const int* in_sizes, int n_in,
                              void* d_out, int out_size)
{
    const float* hs = (const float*)d_in[0];
    const float* wq = (const float*)d_in[1];
    const float* wk = (const float*)d_in[2];
    const float* wv = (const float*)d_in[3];
    const float* wo = (const float*)d_in[4];
    const float* bo = (const float*)d_in[5];
    float* out = (float*)d_out;

    cudaFuncSetAttribute(attn_tc,
                         cudaFuncAttributeMaxDynamicSharedMemorySize, ATTN_SMEM);

    qkv_gemm_tc<<<dim3(4, 128, 3), 256>>>(hs, wq, wk, wv);
    attn_tc<<<dim3(SQ / 64, NHB), 128, ATTN_SMEM>>>();
    out_gemm_tc<<<dim3(4, 128), 256>>>(wo, bo, out);
}

// round 3
// speedup vs baseline: 3.6788x; 1.1809x over previous
#include <cuda_runtime.h>

#define SQ    8192
#define DH    64
#define NHB   16
#define M_TOT 16384
#define DM    512

// g_q holds tf32(q * 0.125 * log2e); g_k, g_v hold tf32(k), tf32(v).
__device__ float g_q[(size_t)NHB * SQ * DH];
__device__ float g_k[(size_t)NHB * SQ * DH];
__device__ float g_v[(size_t)NHB * SQ * DH];
__device__ float g_o[(size_t)NHB * SQ * DH];

__device__ __forceinline__ unsigned f2tf(float x) {
    unsigned r; asm("cvt.rna.tf32.f32 %0, %1;" : "=r"(r) : "f"(x)); return r;
}
__device__ __forceinline__ float ex2(float x) {
    float r; asm("ex2.approx.ftz.f32 %0, %1;" : "=f"(r) : "f"(x)); return r;
}
__device__ __forceinline__ void mma_tf32(float c[4], const unsigned a[4], const unsigned b[2]) {
    asm volatile("mma.sync.aligned.m16n8k8.row.col.f32.tf32.tf32.f32 "
                 "{%0,%1,%2,%3}, {%4,%5,%6,%7}, {%8,%9}, {%0,%1,%2,%3};\n"
                 : "+f"(c[0]), "+f"(c[1]), "+f"(c[2]), "+f"(c[3])
                 : "r"(a[0]), "r"(a[1]), "r"(a[2]), "r"(a[3]),
                   "r"(b[0]), "r"(b[1]));
}
__device__ __forceinline__ void cp16(void* smem, const void* g) {
    unsigned s = (unsigned)__cvta_generic_to_shared(smem);
    asm volatile("cp.async.cg.shared.global [%0], [%1], 16;\n" :: "r"(s), "l"(g));
}

// ---------------------------------------------------------------------------
// QKV projection (tf32 mma). Outputs pre-converted to tf32 bit patterns.
// q additionally scaled by 0.125 * log2(e) so attention works in exp2 domain.
// ---------------------------------------------------------------------------
__global__ __launch_bounds__(256) void qkv_gemm_tc(
    const float* __restrict__ hs,
    const float* __restrict__ wq,
    const float* __restrict__ wk,
    const float* __restrict__ wv)
{
    const int which = blockIdx.z;
    const float* __restrict__ w = (which == 0) ? wq : (which == 1) ? wk : wv;
    float* __restrict__ outb = (which == 0) ? g_q : (which == 1) ? g_k : g_v;
    const float scale = (which == 0) ? 0.125f * 1.4426950408889634f : 1.0f;

    __shared__ unsigned As[16][136];
    __shared__ unsigned Bs[16][136];

    const int tid  = threadIdx.x;
    const int wid  = tid >> 5;
    const int lane = tid & 31;
    const int gid  = lane >> 2;
    const int tig  = lane & 3;
    const int wm = wid & 1, wn = wid >> 1;
    const int row0 = blockIdx.y * 128;
    const int col0 = blockIdx.x * 128;

    float acc[4][4][4];
#pragma unroll
    for (int i = 0; i < 4; i++)
#pragma unroll
        for (int j = 0; j < 4; j++)
#pragma unroll
            for (int p = 0; p < 4; p++) acc[i][j][p] = 0.f;

    const int am0 = wm * 64 + gid;
    const int bn0 = wn * 32 + gid;

    for (int kt = 0; kt < DM; kt += 16) {
        __syncthreads();
#pragma unroll
        for (int r = 0; r < 2; r++) {
            int idx = tid + r * 256;
            int m = idx >> 2, kq = idx & 3;
            float4 v = *(const float4*)&hs[(size_t)(row0 + m) * DM + kt + kq * 4];
            As[kq * 4 + 0][m] = f2tf(v.x);
            As[kq * 4 + 1][m] = f2tf(v.y);
            As[kq * 4 + 2][m] = f2tf(v.z);
            As[kq * 4 + 3][m] = f2tf(v.w);
            int kr = idx >> 5, c4 = idx & 31;
            float4 bv = *(const float4*)&w[(size_t)(kt + kr) * DM + col0 + c4 * 4];
            Bs[kr][c4 * 4 + 0] = f2tf(bv.x);
            Bs[kr][c4 * 4 + 1] = f2tf(bv.y);
            Bs[kr][c4 * 4 + 2] = f2tf(bv.z);
            Bs[kr][c4 * 4 + 3] = f2tf(bv.w);
        }
        __syncthreads();

#pragma unroll
        for (int kk = 0; kk < 16; kk += 8) {
            unsigned a[4][4], b[4][2];
#pragma unroll
            for (int mf = 0; mf < 4; mf++) {
                a[mf][0] = As[kk + tig][am0 + mf * 16];
                a[mf][1] = As[kk + tig][am0 + mf * 16 + 8];
                a[mf][2] = As[kk + tig + 4][am0 + mf * 16];
                a[mf][3] = As[kk + tig + 4][am0 + mf * 16 + 8];
            }
#pragma unroll
            for (int nf = 0; nf < 4; nf++) {
                b[nf][0] = Bs[kk + tig][bn0 + nf * 8];
                b[nf][1] = Bs[kk + tig + 4][bn0 + nf * 8];
            }
#pragma unroll
            for (int mf = 0; mf < 4; mf++)
#pragma unroll
                for (int nf = 0; nf < 4; nf++)
                    mma_tf32(acc[mf][nf], a[mf], b[nf]);
        }
    }

#pragma unroll
    for (int mf = 0; mf < 4; mf++) {
#pragma unroll
        for (int half = 0; half < 2; half++) {
            const int m = row0 + wm * 64 + mf * 16 + gid + half * 8;
            const int b = m >> 13, s = m & (SQ - 1);
            float* obase = outb + (((size_t)(b * 8)) * SQ) * DH + (size_t)s * DH;
#pragma unroll
            for (int nf = 0; nf < 4; nf++) {
                const int n = col0 + wn * 32 + nf * 8 + 2 * tig;
                const int h = n >> 6, d = n & 63;
                float2 o2 = make_float2(
                    __uint_as_float(f2tf(acc[mf][nf][half * 2] * scale)),
                    __uint_as_float(f2tf(acc[mf][nf][half * 2 + 1] * scale)));
                *(float2*)&obase[(size_t)h * SQ * DH + d] = o2;
            }
        }
    }
}

// ---------------------------------------------------------------------------
// Flash attention. grid (SQ/128, NHB), 256 threads (8 warps, 16 q-rows each).
// 4-stage cp.async pipeline over 64-key K/V tiles. Q resident in registers.
// P redistributed warp-locally via shuffles (no smem round trip).
// ---------------------------------------------------------------------------
#define STAGES 4
#define ATTN_SMEM (STAGES * 64 * (68 + 72) * 4)   // 143360 B

__global__ __launch_bounds__(256, 1) void attn_tc()
{
    extern __shared__ __align__(16) unsigned smu[];
    unsigned (*Ks)[64][68] = (unsigned(*)[64][68])smu;                    // [stg][key][d]
    unsigned (*Vs)[64][72] = (unsigned(*)[64][72])(smu + STAGES * 64 * 68);

    const int head = blockIdx.y;
    const size_t hbase = (size_t)head * SQ * DH;
    const float* __restrict__ Q = g_q + hbase;
    const float* __restrict__ K = g_k + hbase;
    const float* __restrict__ V = g_v + hbase;

    const int q0   = blockIdx.x * 128;
    const int tid  = threadIdx.x;
    const int wid  = tid >> 5;
    const int lane = tid & 31;
    const int gid  = lane >> 2;
    const int tig  = lane & 3;

    // Resident Q fragments: rows q0 + wid*16 + gid (+8)
    unsigned qa[8][4];
    {
        const int r0 = q0 + wid * 16 + gid;
#pragma unroll
        for (int kk = 0; kk < 8; kk++) {
            qa[kk][0] = __float_as_uint(__ldg(&Q[(size_t)r0 * DH + kk * 8 + tig]));
            qa[kk][1] = __float_as_uint(__ldg(&Q[(size_t)(r0 + 8) * DH + kk * 8 + tig]));
            qa[kk][2] = __float_as_uint(__ldg(&Q[(size_t)r0 * DH + kk * 8 + tig + 4]));
            qa[kk][3] = __float_as_uint(__ldg(&Q[(size_t)(r0 + 8) * DH + kk * 8 + tig + 4]));
        }
    }

    float oa[8][4];
    float m0 = -1e30f, m1 = -1e30f, l0 = 0.f, l1 = 0.f;
#pragma unroll
    for (int n = 0; n < 8; n++)
#pragma unroll
        for (int p = 0; p < 4; p++) oa[n][p] = 0.f;

    const int NT = SQ / 64;

    // prologue: stage tiles 0, 1
#pragma unroll
    for (int p = 0; p < 2; p++) {
#pragma unroll
        for (int j = 0; j < 4; j++) {
            int ch = tid + j * 256;
            int r = ch >> 4, c4 = (ch & 15) << 2;
            cp16(&Ks[p][r][c4], &K[(size_t)(p * 64 + r) * DH + c4]);
            cp16(&Vs[p][r][c4], &V[(size_t)(p * 64 + r) * DH + c4]);
        }
        asm volatile("cp.async.commit_group;\n");
    }

    for (int t = 0; t < NT; t++) {
        const int cur = t & (STAGES - 1);
        const int nt = t + 2;
        if (nt < NT) {
            const int s = nt & (STAGES - 1);
            const int kt = nt * 64;
#pragma unroll
            for (int j = 0; j < 4; j++) {
                int ch = tid + j * 256;
                int r = ch >> 4, c4 = (ch & 15) << 2;
                cp16(&Ks[s][r][c4], &K[(size_t)(kt + r) * DH + c4]);
                cp16(&Vs[s][r][c4], &V[(size_t)(kt + r) * DH + c4]);
            }
        }
        asm volatile("cp.async.commit_group;\n");
        asm volatile("cp.async.wait_group 2;\n");
        __syncthreads();

        // S = Q K^T
        float sa[8][4];
#pragma unroll
        for (int n = 0; n < 8; n++)
#pragma unroll
            for (int p = 0; p < 4; p++) sa[n][p] = 0.f;

#pragma unroll
        for (int n = 0; n < 8; n++) {
#pragma unroll
            for (int kk = 0; kk < 8; kk++) {
                unsigned b[2];
                b[0] = Ks[cur][n * 8 + gid][kk * 8 + tig];
                b[1] = Ks[cur][n * 8 + gid][kk * 8 + tig + 4];
                mma_tf32(sa[n], qa[kk], b);
            }
        }

        // online softmax (exp2 domain; log2e folded into q)
        float tm0 = -1e30f, tm1 = -1e30f;
#pragma unroll
        for (int n = 0; n < 8; n++) {
            tm0 = fmaxf(tm0, fmaxf(sa[n][0], sa[n][1]));
            tm1 = fmaxf(tm1, fmaxf(sa[n][2], sa[n][3]));
        }
        tm0 = fmaxf(tm0, __shfl_xor_sync(0xffffffffu, tm0, 1));
        tm0 = fmaxf(tm0, __shfl_xor_sync(0xffffffffu, tm0, 2));
        tm1 = fmaxf(tm1, __shfl_xor_sync(0xffffffffu, tm1, 1));
        tm1 = fmaxf(tm1, __shfl_xor_sync(0xffffffffu, tm1, 2));

        const float mn0 = fmaxf(m0, tm0), mn1 = fmaxf(m1, tm1);
        const float corr0 = ex2(m0 - mn0), corr1 = ex2(m1 - mn1);
        m0 = mn0; m1 = mn1;

        float rs0 = 0.f, rs1 = 0.f;
#pragma unroll
        for (int n = 0; n < 8; n++) {
            sa[n][0] = ex2(sa[n][0] - mn0);
            sa[n][1] = ex2(sa[n][1] - mn0);
            sa[n][2] = ex2(sa[n][2] - mn1);
            sa[n][3] = ex2(sa[n][3] - mn1);
            rs0 += sa[n][0] + sa[n][1];
            rs1 += sa[n][2] + sa[n][3];
        }
        rs0 += __shfl_xor_sync(0xffffffffu, rs0, 1);
        rs0 += __shfl_xor_sync(0xffffffffu, rs0, 2);
        rs1 += __shfl_xor_sync(0xffffffffu, rs1, 1);
        rs1 += __shfl_xor_sync(0xffffffffu, rs1, 2);
        l0 = l0 * corr0 + rs0;
        l1 = l1 * corr1 + rs1;

#pragma unroll
        for (int n = 0; n < 8; n++) {
            oa[n][0] *= corr0; oa[n][1] *= corr0;
            oa[n][2] *= corr1; oa[n][3] *= corr1;
        }

        // O += P V, P fragments built by warp shuffles.
        // Owner of P[gid][c]: lane gid*4 + (c>>1), register sa[kk2][c&1];
        // row gid+8 -> registers sa[kk2][2 + (c&1)].
        const int srcA = (gid << 2) + (tig >> 1);
        const int srcB = srcA + 2;
        const bool par = tig & 1;
#pragma unroll
        for (int kk2 = 0; kk2 < 8; kk2++) {
            float e0 = __shfl_sync(0xffffffffu, sa[kk2][0], srcA);
            float e1 = __shfl_sync(0xffffffffu, sa[kk2][1], srcA);
            float e2 = __shfl_sync(0xffffffffu, sa[kk2][2], srcA);
            float e3 = __shfl_sync(0xffffffffu, sa[kk2][3], srcA);
            float f0 = __shfl_sync(0xffffffffu, sa[kk2][0], srcB);
            float f1 = __shfl_sync(0xffffffffu, sa[kk2][1], srcB);
            float f2 = __shfl_sync(0xffffffffu, sa[kk2][2], srcB);
            float f3 = __shfl_sync(0xffffffffu, sa[kk2][3], srcB);
            unsigned pa[4];
            pa[0] = f2tf(par ? e1 : e0);
            pa[1] = f2tf(par ? e3 : e2);
            pa[2] = f2tf(par ? f1 : f0);
            pa[3] = f2tf(par ? f3 : f2);
#pragma unroll
            for (int n = 0; n < 8; n++) {
                unsigned vb[2];
                vb[0] = Vs[cur][kk2 * 8 + tig][n * 8 + gid];
                vb[1] = Vs[cur][kk2 * 8 + tig + 4][n * 8 + gid];
                mma_tf32(oa[n], pa, vb);
            }
        }
    }

    // epilogue
    float* __restrict__ O = g_o + hbase;
    const float inv0 = 1.f / l0, inv1 = 1.f / l1;
    const int r0 = q0 + wid * 16 + gid;
#pragma unroll
    for (int n = 0; n < 8; n++) {
        const int col = n * 8 + 2 * tig;
        *(float2*)&O[(size_t)r0 * DH + col] =
            make_float2(oa[n][0] * inv0, oa[n][1] * inv0);
        *(float2*)&O[(size_t)(r0 + 8) * DH + col] =
            make_float2(oa[n][2] * inv1, oa[n][3] * inv1);
    }
}

// ---------------------------------------------------------------------------
// Output projection: out = attn @ w_out + b_out (A gathered from head-major g_o).
// ---------------------------------------------------------------------------
__global__ __launch_bounds__(256) void out_gemm_tc(
    const float* __restrict__ w,
    const float* __restrict__ bias,
    float* __restrict__ out)
{
    __shared__ unsigned As[16][136];
    __shared__ unsigned Bs[16][136];

    const int tid  = threadIdx.x;
    const int wid  = tid >> 5;
    const int lane = tid & 31;
    const int gid  = lane >> 2;
    const int tig  = lane & 3;
    const int wm = wid & 1, wn = wid >> 1;
    const int row0 = blockIdx.y * 128;
    const int col0 = blockIdx.x * 128;

    float acc[4][4][4];
#pragma unroll
    for (int i = 0; i < 4; i++)
#pragma unroll
        for (int j = 0; j < 4; j++)
#pragma unroll
            for (int p = 0; p < 4; p++) acc[i][j][p] = 0.f;

    const int am0 = wm * 64 + gid;
    const int bn0 = wn * 32 + gid;

    for (int kt = 0; kt < DM; kt += 16) {
        __syncthreads();
#pragma unroll
        for (int r = 0; r < 2; r++) {
            int idx = tid + r * 256;
            int m = row0 + (idx >> 2), kq = idx & 3;
            int k = kt + kq * 4;
            int h = k >> 6, d = k & 63;
            int b = m >> 13, s = m & (SQ - 1);
            float4 v = *(const float4*)&g_o[(((size_t)(b * 8 + h)) * SQ + s) * DH + d];
            As[kq * 4 + 0][idx >> 2] = f2tf(v.x);
            As[kq * 4 + 1][idx >> 2] = f2tf(v.y);
            As[kq * 4 + 2][idx >> 2] = f2tf(v.z);
            As[kq * 4 + 3][idx >> 2] = f2tf(v.w);
            int kr = idx >> 5, c4 = idx & 31;
            float4 bv = *(const float4*)&w[(size_t)(kt + kr) * DM + col0 + c4 * 4];
            Bs[kr][c4 * 4 + 0] = f2tf(bv.x);
            Bs[kr][c4 * 4 + 1] = f2tf(bv.y);
            Bs[kr][c4 * 4 + 2] = f2tf(bv.z);
            Bs[kr][c4 * 4 + 3] = f2tf(bv.w);
        }
        __syncthreads();

#pragma unroll
        for (int kk = 0; kk < 16; kk += 8) {
            unsigned a[4][4], b[4][2];
#pragma unroll
            for (int mf = 0; mf < 4; mf++) {
                a[mf][0] = As[kk + tig][am0 + mf * 16];
                a[mf][1] = As[kk + tig][am0 + mf * 16 + 8];
                a[mf][2] = As[kk + tig + 4][am0 + mf * 16];
                a[mf][3] = As[kk + tig + 4][am0 + mf * 16 + 8];
            }
#pragma unroll
            for (int nf = 0; nf < 4; nf++) {
                b[nf][0] = Bs[kk + tig][bn0 + nf * 8];
                b[nf][1] = Bs[kk + tig + 4][bn0 + nf * 8];
            }
#pragma unroll
            for (int mf = 0; mf < 4; mf++)
#pragma unroll
                for (int nf = 0; nf < 4; nf++)
                    mma_tf32(acc[mf][nf], a[mf], b[nf]);
        }
    }

#pragma unroll
    for (int mf = 0; mf < 4; mf++) {
#pragma unroll
        for (int half = 0; half < 2; half++) {
            const int m = row0 + wm * 64 + mf * 16 + gid + half * 8;
#pragma unroll
            for (int nf = 0; nf < 4; nf++) {
                const int n = col0 + wn * 32 + nf * 8 + 2 * tig;
                float2 o2 = make_float2(acc[mf][nf][half * 2] + bias[n],
                                        acc[mf][nf][half * 2 + 1] + bias[n + 1]);
                *(float2*)&out[(size_t)m * DM + n] = o2;
            }
        }
    }
}

// ---------------------------------------------------------------------------
extern "C" void kernel_launch(void* const* d_in, const int* in_sizes, int n_in,
                              void* d_out, int out_size)
{
    const float* hs = (const float*)d_in[0];
    const float* wq = (const float*)d_in[1];
    const float* wk = (const float*)d_in[2];
    const float* wv = (const float*)d_in[3];
    const float* wo = (const float*)d_in[4];
    const float* bo = (const float*)d_in[5];
    float* out = (float*)d_out;

    cudaFuncSetAttribute(attn_tc,
                         cudaFuncAttributeMaxDynamicSharedMemorySize, ATTN_SMEM);

    qkv_gemm_tc<<<dim3(4, 128, 3), 256>>>(hs, wq, wk, wv);
    attn_tc<<<dim3(SQ / 128, NHB), 256, ATTN_SMEM>>>();
    out_gemm_tc<<<dim3(4, 128), 256>>>(wo, bo, out);
}

// round 5
// speedup vs baseline: 3.8820x; 1.0553x over previous
#include <cuda_runtime.h>

#define SQ    8192
#define DH    64
#define NHB   16
#define M_TOT 16384
#define DM    512

// g_q holds tf32(q * 0.125 * log2e); g_k, g_v hold tf32(k), tf32(v).
__device__ float g_q[(size_t)NHB * SQ * DH];
__device__ float g_k[(size_t)NHB * SQ * DH];
__device__ float g_v[(size_t)NHB * SQ * DH];
__device__ float g_o[(size_t)NHB * SQ * DH];

__device__ __forceinline__ unsigned f2tf(float x) {
    unsigned r; asm("cvt.rna.tf32.f32 %0, %1;" : "=r"(r) : "f"(x)); return r;
}
__device__ __forceinline__ float ex2(float x) {
    float r; asm("ex2.approx.ftz.f32 %0, %1;" : "=f"(r) : "f"(x)); return r;
}
__device__ __forceinline__ void mma_tf32(float c[4], const unsigned a[4], const unsigned b[2]) {
    asm volatile("mma.sync.aligned.m16n8k8.row.col.f32.tf32.tf32.f32 "
                 "{%0,%1,%2,%3}, {%4,%5,%6,%7}, {%8,%9}, {%0,%1,%2,%3};\n"
                 : "+f"(c[0]), "+f"(c[1]), "+f"(c[2]), "+f"(c[3])
                 : "r"(a[0]), "r"(a[1]), "r"(a[2]), "r"(a[3]),
                   "r"(b[0]), "r"(b[1]));
}
__device__ __forceinline__ void cp16(void* smem, const void* g) {
    unsigned s = (unsigned)__cvta_generic_to_shared(smem);
    asm volatile("cp.async.cg.shared.global [%0], [%1], 16;\n" :: "r"(s), "l"(g));
}

// ---------------------------------------------------------------------------
// QKV projection (tf32 mma). Outputs pre-converted to tf32 bit patterns.
// q additionally scaled by 0.125 * log2(e) so attention works in exp2 domain.
// ---------------------------------------------------------------------------
__global__ __launch_bounds__(256) void qkv_gemm_tc(
    const float* __restrict__ hs,
    const float* __restrict__ wq,
    const float* __restrict__ wk,
    const float* __restrict__ wv)
{
    const int which = blockIdx.z;
    const float* __restrict__ w = (which == 0) ? wq : (which == 1) ? wk : wv;
    float* __restrict__ outb = (which == 0) ? g_q : (which == 1) ? g_k : g_v;
    const float scale = (which == 0) ? 0.125f * 1.4426950408889634f : 1.0f;

    __shared__ unsigned As[16][136];
    __shared__ unsigned Bs[16][136];

    const int tid  = threadIdx.x;
    const int wid  = tid >> 5;
    const int lane = tid & 31;
    const int gid  = lane >> 2;
    const int tig  = lane & 3;
    const int wm = wid & 1, wn = wid >> 1;
    const int row0 = blockIdx.y * 128;
    const int col0 = blockIdx.x * 128;

    float acc[4][4][4];
#pragma unroll
    for (int i = 0; i < 4; i++)
#pragma unroll
        for (int j = 0; j < 4; j++)
#pragma unroll
            for (int p = 0; p < 4; p++) acc[i][j][p] = 0.f;

    const int am0 = wm * 64 + gid;
    const int bn0 = wn * 32 + gid;

    for (int kt = 0; kt < DM; kt += 16) {
        __syncthreads();
#pragma unroll
        for (int r = 0; r < 2; r++) {
            int idx = tid + r * 256;
            int m = idx >> 2, kq = idx & 3;
            float4 v = *(const float4*)&hs[(size_t)(row0 + m) * DM + kt + kq * 4];
            As[kq * 4 + 0][m] = f2tf(v.x);
            As[kq * 4 + 1][m] = f2tf(v.y);
            As[kq * 4 + 2][m] = f2tf(v.z);
            As[kq * 4 + 3][m] = f2tf(v.w);
            int kr = idx >> 5, c4 = idx & 31;
            float4 bv = *(const float4*)&w[(size_t)(kt + kr) * DM + col0 + c4 * 4];
            Bs[kr][c4 * 4 + 0] = f2tf(bv.x);
            Bs[kr][c4 * 4 + 1] = f2tf(bv.y);
            Bs[kr][c4 * 4 + 2] = f2tf(bv.z);
            Bs[kr][c4 * 4 + 3] = f2tf(bv.w);
        }
        __syncthreads();

#pragma unroll
        for (int kk = 0; kk < 16; kk += 8) {
            unsigned a[4][4], b[4][2];
#pragma unroll
            for (int mf = 0; mf < 4; mf++) {
                a[mf][0] = As[kk + tig][am0 + mf * 16];
                a[mf][1] = As[kk + tig][am0 + mf * 16 + 8];
                a[mf][2] = As[kk + tig + 4][am0 + mf * 16];
                a[mf][3] = As[kk + tig + 4][am0 + mf * 16 + 8];
            }
#pragma unroll
            for (int nf = 0; nf < 4; nf++) {
                b[nf][0] = Bs[kk + tig][bn0 + nf * 8];
                b[nf][1] = Bs[kk + tig + 4][bn0 + nf * 8];
            }
#pragma unroll
            for (int mf = 0; mf < 4; mf++)
#pragma unroll
                for (int nf = 0; nf < 4; nf++)
                    mma_tf32(acc[mf][nf], a[mf], b[nf]);
        }
    }

#pragma unroll
    for (int mf = 0; mf < 4; mf++) {
#pragma unroll
        for (int half = 0; half < 2; half++) {
            const int m = row0 + wm * 64 + mf * 16 + gid + half * 8;
            const int b = m >> 13, s = m & (SQ - 1);
            float* obase = outb + (((size_t)(b * 8)) * SQ) * DH + (size_t)s * DH;
#pragma unroll
            for (int nf = 0; nf < 4; nf++) {
                const int n = col0 + wn * 32 + nf * 8 + 2 * tig;
                const int h = n >> 6, d = n & 63;
                float2 o2 = make_float2(
                    __uint_as_float(f2tf(acc[mf][nf][half * 2] * scale)),
                    __uint_as_float(f2tf(acc[mf][nf][half * 2 + 1] * scale)));
                *(float2*)&obase[(size_t)h * SQ * DH + d] = o2;
            }
        }
    }
}

// ---------------------------------------------------------------------------
// Flash attention. grid (SQ/256, NHB), 256 threads (8 warps x 32 q-rows).
// Each warp owns two m16 fragments; K/V fragments loaded once and reused by
// both, halving smem-crossbar traffic per q-row. 4-stage cp.async pipeline.
// ---------------------------------------------------------------------------
#define STAGES 4
#define ATTN_SMEM (STAGES * 64 * (68 + 72) * 4)   // 143360 B

__global__ __launch_bounds__(256, 1) void attn_tc()
{
    extern __shared__ __align__(16) unsigned smu[];
    unsigned (*Ks)[64][68] = (unsigned(*)[64][68])smu;                    // [stg][key][d]
    unsigned (*Vs)[64][72] = (unsigned(*)[64][72])(smu + STAGES * 64 * 68);

    const int head = blockIdx.y;
    const size_t hbase = (size_t)head * SQ * DH;
    const float* __restrict__ Q = g_q + hbase;
    const float* __restrict__ K = g_k + hbase;
    const float* __restrict__ V = g_v + hbase;

    const int q0   = blockIdx.x * 256;
    const int tid  = threadIdx.x;
    const int wid  = tid >> 5;
    const int lane = tid & 31;
    const int gid  = lane >> 2;
    const int tig  = lane & 3;

    // Resident Q fragments: frag f covers rows q0 + wid*32 + f*16 + {gid, gid+8}
    unsigned qa[2][8][4];
#pragma unroll
    for (int f = 0; f < 2; f++) {
        const int r0 = q0 + wid * 32 + f * 16 + gid;
#pragma unroll
        for (int kk = 0; kk < 8; kk++) {
            qa[f][kk][0] = __float_as_uint(__ldg(&Q[(size_t)r0 * DH + kk * 8 + tig]));
            qa[f][kk][1] = __float_as_uint(__ldg(&Q[(size_t)(r0 + 8) * DH + kk * 8 + tig]));
            qa[f][kk][2] = __float_as_uint(__ldg(&Q[(size_t)r0 * DH + kk * 8 + tig + 4]));
            qa[f][kk][3] = __float_as_uint(__ldg(&Q[(size_t)(r0 + 8) * DH + kk * 8 + tig + 4]));
        }
    }

    float oa[2][8][4];
    float mr[2][2], lr[2][2];
#pragma unroll
    for (int f = 0; f < 2; f++) {
        mr[f][0] = -1e30f; mr[f][1] = -1e30f;
        lr[f][0] = 0.f;    lr[f][1] = 0.f;
#pragma unroll
        for (int n = 0; n < 8; n++)
#pragma unroll
            for (int p = 0; p < 4; p++) oa[f][n][p] = 0.f;
    }

    const int NT = SQ / 64;

    // prologue: stage tiles 0, 1
#pragma unroll
    for (int p = 0; p < 2; p++) {
#pragma unroll
        for (int j = 0; j < 4; j++) {
            int ch = tid + j * 256;
            int r = ch >> 4, c4 = (ch & 15) << 2;
            cp16(&Ks[p][r][c4], &K[(size_t)(p * 64 + r) * DH + c4]);
            cp16(&Vs[p][r][c4], &V[(size_t)(p * 64 + r) * DH + c4]);
        }
        asm volatile("cp.async.commit_group;\n");
    }

    for (int t = 0; t < NT; t++) {
        const int cur = t & (STAGES - 1);
        const int nt = t + 2;
        if (nt < NT) {
            const int s = nt & (STAGES - 1);
            const int kt = nt * 64;
#pragma unroll
            for (int j = 0; j < 4; j++) {
                int ch = tid + j * 256;
                int r = ch >> 4, c4 = (ch & 15) << 2;
                cp16(&Ks[s][r][c4], &K[(size_t)(kt + r) * DH + c4]);
                cp16(&Vs[s][r][c4], &V[(size_t)(kt + r) * DH + c4]);
            }
        }
        asm volatile("cp.async.commit_group;\n");
        asm volatile("cp.async.wait_group 2;\n");
        __syncthreads();

        // S = Q K^T : K fragments loaded once, reused by both m-fragments
        float sa[2][8][4];
#pragma unroll
        for (int f = 0; f < 2; f++)
#pragma unroll
            for (int n = 0; n < 8; n++)
#pragma unroll
                for (int p = 0; p < 4; p++) sa[f][n][p] = 0.f;

#pragma unroll
        for (int n = 0; n < 8; n++) {
#pragma unroll
            for (int kk = 0; kk < 8; kk++) {
                unsigned b[2];
                b[0] = Ks[cur][n * 8 + gid][kk * 8 + tig];
                b[1] = Ks[cur][n * 8 + gid][kk * 8 + tig + 4];
                mma_tf32(sa[0][n], qa[0][kk], b);
                mma_tf32(sa[1][n], qa[1][kk], b);
            }
        }

        // online softmax per fragment (exp2 domain)
#pragma unroll
        for (int f = 0; f < 2; f++) {
            float tm0 = -1e30f, tm1 = -1e30f;
#pragma unroll
            for (int n = 0; n < 8; n++) {
                tm0 = fmaxf(tm0, fmaxf(sa[f][n][0], sa[f][n][1]));
                tm1 = fmaxf(tm1, fmaxf(sa[f][n][2], sa[f][n][3]));
            }
            tm0 = fmaxf(tm0, __shfl_xor_sync(0xffffffffu, tm0, 1));
            tm0 = fmaxf(tm0, __shfl_xor_sync(0xffffffffu, tm0, 2));
            tm1 = fmaxf(tm1, __shfl_xor_sync(0xffffffffu, tm1, 1));
            tm1 = fmaxf(tm1, __shfl_xor_sync(0xffffffffu, tm1, 2));

            const float mn0 = fmaxf(mr[f][0], tm0), mn1 = fmaxf(mr[f][1], tm1);
            const float corr0 = ex2(mr[f][0] - mn0), corr1 = ex2(mr[f][1] - mn1);
            mr[f][0] = mn0; mr[f][1] = mn1;

            float rs0 = 0.f, rs1 = 0.f;
#pragma unroll
            for (int n = 0; n < 8; n++) {
                sa[f][n][0] = ex2(sa[f][n][0] - mn0);
                sa[f][n][1] = ex2(sa[f][n][1] - mn0);
                sa[f][n][2] = ex2(sa[f][n][2] - mn1);
                sa[f][n][3] = ex2(sa[f][n][3] - mn1);
                rs0 += sa[f][n][0] + sa[f][n][1];
                rs1 += sa[f][n][2] + sa[f][n][3];
            }
            rs0 += __shfl_xor_sync(0xffffffffu, rs0, 1);
            rs0 += __shfl_xor_sync(0xffffffffu, rs0, 2);
            rs1 += __shfl_xor_sync(0xffffffffu, rs1, 1);
            rs1 += __shfl_xor_sync(0xffffffffu, rs1, 2);
            lr[f][0] = lr[f][0] * corr0 + rs0;
            lr[f][1] = lr[f][1] * corr1 + rs1;

#pragma unroll
            for (int n = 0; n < 8; n++) {
                oa[f][n][0] *= corr0; oa[f][n][1] *= corr0;
                oa[f][n][2] *= corr1; oa[f][n][3] *= corr1;
            }
        }

        // O += P V. P fragments via warp shuffles; V fragments reused by both f.
        const int srcA = (gid << 2) + (tig >> 1);
        const int srcB = srcA + 2;
        const bool par = tig & 1;
#pragma unroll
        for (int kk2 = 0; kk2 < 8; kk2++) {
            unsigned pa[2][4];
#pragma unroll
            for (int f = 0; f < 2; f++) {
                float e0 = __shfl_sync(0xffffffffu, sa[f][kk2][0], srcA);
                float e1 = __shfl_sync(0xffffffffu, sa[f][kk2][1], srcA);
                float e2 = __shfl_sync(0xffffffffu, sa[f][kk2][2], srcA);
                float e3 = __shfl_sync(0xffffffffu, sa[f][kk2][3], srcA);
                float f0 = __shfl_sync(0xffffffffu, sa[f][kk2][0], srcB);
                float f1 = __shfl_sync(0xffffffffu, sa[f][kk2][1], srcB);
                float f2 = __shfl_sync(0xffffffffu, sa[f][kk2][2], srcB);
                float f3 = __shfl_sync(0xffffffffu, sa[f][kk2][3], srcB);
                pa[f][0] = f2tf(par ? e1 : e0);
                pa[f][1] = f2tf(par ? e3 : e2);
                pa[f][2] = f2tf(par ? f1 : f0);
                pa[f][3] = f2tf(par ? f3 : f2);
            }
#pragma unroll
            for (int n = 0; n < 8; n++) {
                unsigned vb[2];
                vb[0] = Vs[cur][kk2 * 8 + tig][n * 8 + gid];
                vb[1] = Vs[cur][kk2 * 8 + tig + 4][n * 8 + gid];
                mma_tf32(oa[0][n], pa[0], vb);
                mma_tf32(oa[1][n], pa[1], vb);
            }
        }
    }

    // epilogue
    float* __restrict__ O = g_o + hbase;
#pragma unroll
    for (int f = 0; f < 2; f++) {
        const float inv0 = 1.f / lr[f][0], inv1 = 1.f / lr[f][1];
        const int r0 = q0 + wid * 32 + f * 16 + gid;
#pragma unroll
        for (int n = 0; n < 8; n++) {
            const int col = n * 8 + 2 * tig;
            *(float2*)&O[(size_t)r0 * DH + col] =
                make_float2(oa[f][n][0] * inv0, oa[f][n][1] * inv0);
            *(float2*)&O[(size_t)(r0 + 8) * DH + col] =
                make_float2(oa[f][n][2] * inv1, oa[f][n][3] * inv1);
        }
    }
}

// ---------------------------------------------------------------------------
// Output projection: out = attn @ w_out + b_out (A gathered from head-major g_o).
// ---------------------------------------------------------------------------
__global__ __launch_bounds__(256) void out_gemm_tc(
    const float* __restrict__ w,
    const float* __restrict__ bias,
    float* __restrict__ out)
{
    __shared__ unsigned As[16][136];
    __shared__ unsigned Bs[16][136];

    const int tid  = threadIdx.x;
    const int wid  = tid >> 5;
    const int lane = tid & 31;
    const int gid  = lane >> 2;
    const int tig  = lane & 3;
    const int wm = wid & 1, wn = wid >> 1;
    const int row0 = blockIdx.y * 128;
    const int col0 = blockIdx.x * 128;

    float acc[4][4][4];
#pragma unroll
    for (int i = 0; i < 4; i++)
#pragma unroll
        for (int j = 0; j < 4; j++)
#pragma unroll
            for (int p = 0; p < 4; p++) acc[i][j][p] = 0.f;

    const int am0 = wm * 64 + gid;
    const int bn0 = wn * 32 + gid;

    for (int kt = 0; kt < DM; kt += 16) {
        __syncthreads();
#pragma unroll
        for (int r = 0; r < 2; r++) {
            int idx = tid + r * 256;
            int m = row0 + (idx >> 2), kq = idx & 3;
            int k = kt + kq * 4;
            int h = k >> 6, d = k & 63;
            int b = m >> 13, s = m & (SQ - 1);
            float4 v = *(const float4*)&g_o[(((size_t)(b * 8 + h)) * SQ + s) * DH + d];
            As[kq * 4 + 0][idx >> 2] = f2tf(v.x);
            As[kq * 4 + 1][idx >> 2] = f2tf(v.y);
            As[kq * 4 + 2][idx >> 2] = f2tf(v.z);
            As[kq * 4 + 3][idx >> 2] = f2tf(v.w);
            int kr = idx >> 5, c4 = idx & 31;
            float4 bv = *(const float4*)&w[(size_t)(kt + kr) * DM + col0 + c4 * 4];
            Bs[kr][c4 * 4 + 0] = f2tf(bv.x);
            Bs[kr][c4 * 4 + 1] = f2tf(bv.y);
            Bs[kr][c4 * 4 + 2] = f2tf(bv.z);
            Bs[kr][c4 * 4 + 3] = f2tf(bv.w);
        }
        __syncthreads();

#pragma unroll
        for (int kk = 0; kk < 16; kk += 8) {
            unsigned a[4][4], b[4][2];
#pragma unroll
            for (int mf = 0; mf < 4; mf++) {
                a[mf][0] = As[kk + tig][am0 + mf * 16];
                a[mf][1] = As[kk + tig][am0 + mf * 16 + 8];
                a[mf][2] = As[kk + tig + 4][am0 + mf * 16];
                a[mf][3] = As[kk + tig + 4][am0 + mf * 16 + 8];
            }
#pragma unroll
            for (int nf = 0; nf < 4; nf++) {
                b[nf][0] = Bs[kk + tig][bn0 + nf * 8];
                b[nf][1] = Bs[kk + tig + 4][bn0 + nf * 8];
            }
#pragma unroll
            for (int mf = 0; mf < 4; mf++)
#pragma unroll
                for (int nf = 0; nf < 4; nf++)
                    mma_tf32(acc[mf][nf], a[mf], b[nf]);
        }
    }

#pragma unroll
    for (int mf = 0; mf < 4; mf++) {
#pragma unroll
        for (int half = 0; half < 2; half++) {
            const int m = row0 + wm * 64 + mf * 16 + gid + half * 8;
#pragma unroll
            for (int nf = 0; nf < 4; nf++) {
                const int n = col0 + wn * 32 + nf * 8 + 2 * tig;
                float2 o2 = make_float2(acc[mf][nf][half * 2] + bias[n],
                                        acc[mf][nf][half * 2 + 1] + bias[n + 1]);
                *(float2*)&out[(size_t)m * DM + n] = o2;
            }
        }
    }
}

// ---------------------------------------------------------------------------
extern "C" void kernel_launch(void* const* d_in, const int* in_sizes, int n_in,
                              void* d_out, int out_size)
{
    const float* hs = (const float*)d_in[0];
    const float* wq = (const float*)d_in[1];
    const float* wk = (const float*)d_in[2];
    const float* wv = (const float*)d_in[3];
    const float* wo = (const float*)d_in[4];
    const float* bo = (const float*)d_in[5];
    float* out = (float*)d_out;

    cudaFuncSetAttribute(attn_tc,
                         cudaFuncAttributeMaxDynamicSharedMemorySize, ATTN_SMEM);

    qkv_gemm_tc<<<dim3(4, 128, 3), 256>>>(hs, wq, wk, wv);
    attn_tc<<<dim3(SQ / 256, NHB), 256, ATTN_SMEM>>>();
    out_gemm_tc<<<dim3(4, 128), 256>>>(wo, bo, out);
}